// round 1
// baseline (speedup 1.0000x reference)
#include <cuda_runtime.h>
#include <math.h>
#include <stdint.h>

// ---------------------------------------------------------------------------
// TextGRUClassifier: 2-layer bidirectional GRU (B=256,T=512,E=128,H=160) + FC head
//
// Pipeline (all fp32, round-1 baseline):
//   K0 pack    : repack the 4 Whh matrices into [dl][k/4][g][4] float4 layout
//   K1 gates0  : gi0[d][t*B+b][480] = Wih_l0{f,b} @ emb[x[b,t]] + bih   (GEMM, K=128, gather)
//   K2 scan0   : per-CTA batch-chunk GRU scan (both dirs), writes y0[t][b][320]
//   K3 gates1  : gi1[d][m][480] = Wih_l1{f,b} @ y0[m] + bih             (GEMM, K=320)
//   K4 scan1   : same scan, keeps only final h -> hfin[2][256][160]
//   K5 head    : out[b] = fc2( relu( fc1( concat(hf,hb) ) ) )
// ---------------------------------------------------------------------------

#define Tt 512
#define Bb 256
#define Ee 128
#define Hh 160
#define G3 480          // 3*H
#define Mrows (Tt*Bb)   // 131072

// ---- scratch (static device globals; no allocation in kernel_launch) ----
static __device__ float g_gi0[(size_t)2 * Mrows * G3];   // 503 MB
static __device__ float g_gi1[(size_t)2 * Mrows * G3];   // 503 MB
static __device__ float g_y0[(size_t)Mrows * 320];       // 168 MB
static __device__ float g_whhP[4 * 40 * G3 * 4];         // packed Whh, 1.2 MB
static __device__ float g_hfin[2 * Bb * Hh];

// ---------------------------------------------------------------------------
// K0: pack Whh[g][k] -> whhP[dl][k/4][g][k%4]  (so a thread `g` loads float4 of 4 k's)
// ---------------------------------------------------------------------------
__global__ void pack_whh_kernel(const float* __restrict__ w0f, const float* __restrict__ w0b,
                                const float* __restrict__ w1f, const float* __restrict__ w1b,
                                float* __restrict__ wp) {
    int dl = blockIdx.x;
    const float* w = (dl == 0) ? w0f : (dl == 1) ? w0b : (dl == 2) ? w1f : w1b;
    for (int i = threadIdx.x; i < G3 * Hh; i += blockDim.x) {
        int g = i / Hh, k = i % Hh;
        wp[(((size_t)dl * 40 + (k >> 2)) * G3 + g) * 4 + (k & 3)] = w[i];
    }
}

// ---------------------------------------------------------------------------
// K1/K3: gates GEMM.  out[dir][m][n] = dot(W_dir[n][0:K], A_row(m)) + bias_dir[n]
//   A_row(m) = emb[x[b,t]] (GATHER) or y0[m]   with m = t*B + b
//   Tile: BM=64 x BN=96 x BK=32, 256 threads, 4x6 register tile per thread.
// ---------------------------------------------------------------------------
template <int KDIM, bool GATHER>
__global__ __launch_bounds__(256)
void gates_gemm_kernel(const float* __restrict__ A, const int* __restrict__ xids,
                       const float* __restrict__ Wf, const float* __restrict__ Wb,
                       const float* __restrict__ bf, const float* __restrict__ bb,
                       float* __restrict__ out) {
    const int m0 = blockIdx.x * 64;
    const int n0 = blockIdx.y * 96;
    const int dir = blockIdx.z;
    const float* W = dir ? Wb : Wf;
    const float* bias = dir ? bb : bf;
    float* outp = out + (size_t)dir * Mrows * G3;

    __shared__ float As[32][65];
    __shared__ float Bs[32][97];
    __shared__ int rid[64];

    const int tid = threadIdx.x;

    if (GATHER) {
        if (tid < 64) {
            int m = m0 + tid;
            int t = m >> 8;     // m / 256
            int b = m & 255;    // m % 256
            rid[tid] = xids[b * Tt + t];
        }
        __syncthreads();
    }

    const int ty = tid >> 4;       // 0..15 -> rows ty*4 .. ty*4+3
    const int tx = tid & 15;       // 0..15 -> cols tx*6 .. tx*6+5

    float acc[4][6];
#pragma unroll
    for (int i = 0; i < 4; i++)
#pragma unroll
        for (int j = 0; j < 6; j++) acc[i][j] = 0.f;

    for (int k0 = 0; k0 < KDIM; k0 += 32) {
        // --- load A tile: 64 rows x 32 k  (512 float4, 2 per thread) ---
#pragma unroll
        for (int u = 0; u < 2; u++) {
            int idx = tid * 2 + u;          // 0..511
            int r = idx >> 3;               // 0..63
            int c4 = idx & 7;               // 0..7
            const float* arow;
            if (GATHER) arow = A + (size_t)rid[r] * KDIM;
            else        arow = A + (size_t)(m0 + r) * KDIM;
            float4 v = *reinterpret_cast<const float4*>(arow + k0 + c4 * 4);
            As[c4 * 4 + 0][r] = v.x;
            As[c4 * 4 + 1][r] = v.y;
            As[c4 * 4 + 2][r] = v.z;
            As[c4 * 4 + 3][r] = v.w;
        }
        // --- load B tile: 96 rows(n) x 32 k  (768 float4, 3 per thread) ---
#pragma unroll
        for (int u = 0; u < 3; u++) {
            int idx = tid * 3 + u;          // 0..767
            int n = idx >> 3;               // 0..95
            int c4 = idx & 7;               // 0..7
            float4 v = *reinterpret_cast<const float4*>(W + (size_t)(n0 + n) * KDIM + k0 + c4 * 4);
            Bs[c4 * 4 + 0][n] = v.x;
            Bs[c4 * 4 + 1][n] = v.y;
            Bs[c4 * 4 + 2][n] = v.z;
            Bs[c4 * 4 + 3][n] = v.w;
        }
        __syncthreads();

#pragma unroll
        for (int kk = 0; kk < 32; kk++) {
            float a[4], b[6];
#pragma unroll
            for (int i = 0; i < 4; i++) a[i] = As[kk][ty * 4 + i];
#pragma unroll
            for (int j = 0; j < 6; j++) b[j] = Bs[kk][tx * 6 + j];
#pragma unroll
            for (int i = 0; i < 4; i++)
#pragma unroll
                for (int j = 0; j < 6; j++) acc[i][j] += a[i] * b[j];
        }
        __syncthreads();
    }

    float bj[6];
#pragma unroll
    for (int j = 0; j < 6; j++) bj[j] = bias[n0 + tx * 6 + j];

#pragma unroll
    for (int i = 0; i < 4; i++) {
        size_t row = (size_t)(m0 + ty * 4 + i) * G3 + n0 + tx * 6;
#pragma unroll
        for (int j = 0; j < 6; j++) outp[row + j] = acc[i][j] + bj[j];
    }
}

// ---------------------------------------------------------------------------
// K2/K4: GRU scan. grid = (64 batch-chunks of 4, 2 dirs), 480 threads.
//   thread g computes gh[g][b] = dot(Whh[g], h[b]) + bhh[g] for 4 batch rows,
//   then threads g<160 do the gate combine + h update.
// ---------------------------------------------------------------------------
__device__ __forceinline__ float sigm_f(float x) {
    return 1.f / (1.f + __expf(-x));
}

__global__ __launch_bounds__(480)
void scan_kernel(const float* __restrict__ gi, const float* __restrict__ wp,
                 const float* __restrict__ bhf, const float* __restrict__ bhb,
                 float* __restrict__ yout, int layer) {
    const int dir = blockIdx.y;
    const int b0 = blockIdx.x * 4;
    const int g = threadIdx.x;       // 0..479

    __shared__ __align__(16) float h_s[Hh * 4];   // h_s[k*4 + b]
    __shared__ float gh_s[4 * G3];                // gh_s[b*480 + g]

    for (int i = g; i < Hh * 4; i += 480) h_s[i] = 0.f;

    const float bh = (dir ? bhb : bhf)[g];
    const float4* wbase = reinterpret_cast<const float4*>(wp) +
                          (size_t)(layer * 2 + dir) * 40 * G3 + g;
    const float* gibase = gi + (size_t)dir * Mrows * G3;

    __syncthreads();

    for (int s = 0; s < Tt; s++) {
        const int t = dir ? (Tt - 1 - s) : s;

        float a0 = bh, a1 = bh, a2 = bh, a3 = bh;
        const float4* hp = reinterpret_cast<const float4*>(h_s);
#pragma unroll 4
        for (int kq = 0; kq < 40; kq++) {
            float4 w = wbase[kq * G3];
            float4 h0 = hp[kq * 4 + 0];
            float4 h1 = hp[kq * 4 + 1];
            float4 h2 = hp[kq * 4 + 2];
            float4 h3 = hp[kq * 4 + 3];
            a0 += w.x * h0.x; a1 += w.x * h0.y; a2 += w.x * h0.z; a3 += w.x * h0.w;
            a0 += w.y * h1.x; a1 += w.y * h1.y; a2 += w.y * h1.z; a3 += w.y * h1.w;
            a0 += w.z * h2.x; a1 += w.z * h2.y; a2 += w.z * h2.z; a3 += w.z * h2.w;
            a0 += w.w * h3.x; a1 += w.w * h3.y; a2 += w.w * h3.z; a3 += w.w * h3.w;
        }
        gh_s[0 * G3 + g] = a0;
        gh_s[1 * G3 + g] = a1;
        gh_s[2 * G3 + g] = a2;
        gh_s[3 * G3 + g] = a3;
        __syncthreads();

        if (g < Hh) {
            const float* grow = gibase + ((size_t)t * Bb + b0) * G3;
#pragma unroll
            for (int b = 0; b < 4; b++) {
                const float* gr = grow + b * G3;
                float ir = gr[g], iz = gr[Hh + g], inn = gr[2 * Hh + g];
                float hr = gh_s[b * G3 + g];
                float hz = gh_s[b * G3 + Hh + g];
                float hn = gh_s[b * G3 + 2 * Hh + g];
                float r = sigm_f(ir + hr);
                float z = sigm_f(iz + hz);
                float n = tanhf(inn + r * hn);
                float hprev = h_s[g * 4 + b];
                float hnew = (1.f - z) * n + z * hprev;
                h_s[g * 4 + b] = hnew;
                if (layer == 0) {
                    yout[((size_t)t * Bb + b0 + b) * 320 + dir * Hh + g] = hnew;
                }
            }
        }
        __syncthreads();
    }

    if (layer == 1 && g < Hh) {
#pragma unroll
        for (int b = 0; b < 4; b++) {
            yout[((size_t)dir * Bb + b0 + b) * Hh + g] = h_s[g * 4 + b];
        }
    }
}

// ---------------------------------------------------------------------------
// K5: head.  out[b] = fc2_b + sum_j relu(fc1_b[j] + fc1_w[j,:] . concat(hf,hb)) * fc2_w[j]
// ---------------------------------------------------------------------------
__global__ __launch_bounds__(128)
void head_kernel(const float* __restrict__ hfin,
                 const float* __restrict__ fc1w, const float* __restrict__ fc1b,
                 const float* __restrict__ fc2w, const float* __restrict__ fc2b,
                 float* __restrict__ out) {
    const int b = blockIdx.x;
    const int j = threadIdx.x;   // 0..127
    __shared__ float hv[320];
    __shared__ float red[4];

    for (int k = j; k < Hh; k += 128) {
        hv[k]       = hfin[(size_t)b * Hh + k];
        hv[Hh + k]  = hfin[(size_t)Bb * Hh + (size_t)b * Hh + k];
    }
    __syncthreads();

    float acc = fc1b[j];
    const float* wr = fc1w + (size_t)j * 320;
#pragma unroll 8
    for (int k = 0; k < 320; k++) acc += wr[k] * hv[k];
    float v = fmaxf(acc, 0.f) * fc2w[j];

#pragma unroll
    for (int o = 16; o > 0; o >>= 1) v += __shfl_down_sync(0xffffffffu, v, o);
    if ((j & 31) == 0) red[j >> 5] = v;
    __syncthreads();
    if (j == 0) out[b] = red[0] + red[1] + red[2] + red[3] + fc2b[0];
}

// ---------------------------------------------------------------------------
// kernel_launch
// ---------------------------------------------------------------------------
extern "C" void kernel_launch(void* const* d_in, const int* in_sizes, int n_in,
                              void* d_out, int out_size) {
    const int*   x        = (const int*)  d_in[0];
    const float* emb      = (const float*)d_in[1];
    const float* Wih_l0f  = (const float*)d_in[2];
    const float* Whh_l0f  = (const float*)d_in[3];
    const float* bih_l0f  = (const float*)d_in[4];
    const float* bhh_l0f  = (const float*)d_in[5];
    const float* Wih_l0b  = (const float*)d_in[6];
    const float* Whh_l0b  = (const float*)d_in[7];
    const float* bih_l0b  = (const float*)d_in[8];
    const float* bhh_l0b  = (const float*)d_in[9];
    const float* Wih_l1f  = (const float*)d_in[10];
    const float* Whh_l1f  = (const float*)d_in[11];
    const float* bih_l1f  = (const float*)d_in[12];
    const float* bhh_l1f  = (const float*)d_in[13];
    const float* Wih_l1b  = (const float*)d_in[14];
    const float* Whh_l1b  = (const float*)d_in[15];
    const float* bih_l1b  = (const float*)d_in[16];
    const float* bhh_l1b  = (const float*)d_in[17];
    const float* fc1_w    = (const float*)d_in[18];
    const float* fc1_b    = (const float*)d_in[19];
    const float* fc2_w    = (const float*)d_in[20];
    const float* fc2_b    = (const float*)d_in[21];
    float* out = (float*)d_out;

    float *gi0, *gi1, *y0, *whhP, *hfin;
    cudaGetSymbolAddress((void**)&gi0,  g_gi0);
    cudaGetSymbolAddress((void**)&gi1,  g_gi1);
    cudaGetSymbolAddress((void**)&y0,   g_y0);
    cudaGetSymbolAddress((void**)&whhP, g_whhP);
    cudaGetSymbolAddress((void**)&hfin, g_hfin);

    // K0: pack recurrent weights
    pack_whh_kernel<<<4, 256>>>(Whh_l0f, Whh_l0b, Whh_l1f, Whh_l1b, whhP);

    // K1: layer-0 input gates (embedding gather GEMM, K=128)
    {
        dim3 grid(Mrows / 64, G3 / 96, 2);
        gates_gemm_kernel<128, true><<<grid, 256>>>(emb, x, Wih_l0f, Wih_l0b,
                                                    bih_l0f, bih_l0b, gi0);
    }

    // K2: layer-0 scan (both directions) -> y0
    scan_kernel<<<dim3(Bb / 4, 2), 480>>>(gi0, whhP, bhh_l0f, bhh_l0b, y0, 0);

    // K3: layer-1 input gates (GEMM over y0, K=320)
    {
        dim3 grid(Mrows / 64, G3 / 96, 2);
        gates_gemm_kernel<320, false><<<grid, 256>>>(y0, nullptr, Wih_l1f, Wih_l1b,
                                                     bih_l1f, bih_l1b, gi1);
    }

    // K4: layer-1 scan -> final hidden states
    scan_kernel<<<dim3(Bb / 4, 2), 480>>>(gi1, whhP, bhh_l1f, bhh_l1b, hfin, 1);

    // K5: FC head
    head_kernel<<<Bb, 128>>>(hfin, fc1_w, fc1_b, fc2_w, fc2_b, out);
}

// round 2
// speedup vs baseline: 1.1965x; 1.1965x over previous
#include <cuda_runtime.h>
#include <math.h>
#include <stdint.h>

// ---------------------------------------------------------------------------
// TextGRUClassifier: 2-layer bidirectional GRU (B=256,T=512,E=128,H=160) + FC
// R2: f32x2 packed math everywhere; scan keeps 26/40 of Whh in smem and each
// thread owns one h-unit (all 3 gate rows) -> no gh smem exchange.
// ---------------------------------------------------------------------------

#define Tt 512
#define Bb 256
#define Hh 160
#define G3 480
#define Mrows (Tt*Bb)     // 131072
#define SKQ 26            // k-quads of Whh kept in smem (of 40)

typedef unsigned long long u64;

// ---- scratch ----
static __device__ float g_gi0[(size_t)2 * Mrows * G3];
static __device__ float g_gi1[(size_t)2 * Mrows * G3];
static __device__ float g_y0[(size_t)Mrows * 320];
static __device__ float g_whhP[4 * 40 * G3 * 4];
static __device__ float g_hfin[2 * Bb * Hh];

// ---- f32x2 helpers ----
__device__ __forceinline__ u64 pack2(float x, float y) {
    u64 r;
    asm("mov.b64 %0, {%1, %2};" : "=l"(r) : "f"(x), "f"(y));
    return r;
}
__device__ __forceinline__ void unpack2(u64 v, float& x, float& y) {
    asm("mov.b64 {%0, %1}, %2;" : "=f"(x), "=f"(y) : "l"(v));
}
__device__ __forceinline__ void fma2(u64& d, u64 a, u64 b) {
    asm("fma.rn.f32x2 %0, %1, %2, %0;" : "+l"(d) : "l"(a), "l"(b));
}
__device__ __forceinline__ float sigm_f(float x) { return 1.f / (1.f + __expf(-x)); }

// ---------------------------------------------------------------------------
// K0: pack Whh[g][k] -> whhP[dl][kq][g][k%4]
// ---------------------------------------------------------------------------
__global__ void pack_whh_kernel(const float* __restrict__ w0f, const float* __restrict__ w0b,
                                const float* __restrict__ w1f, const float* __restrict__ w1b,
                                float* __restrict__ wp) {
    int dl = blockIdx.x;
    const float* w = (dl == 0) ? w0f : (dl == 1) ? w0b : (dl == 2) ? w1f : w1b;
    for (int i = threadIdx.x; i < G3 * Hh; i += blockDim.x) {
        int g = i / Hh, k = i % Hh;
        wp[(((size_t)dl * 40 + (k >> 2)) * G3 + g) * 4 + (k & 3)] = w[i];
    }
}

// ---------------------------------------------------------------------------
// K1/K3: gates GEMM, BM=128 BN=96 BK=16, 256 thr, 8x6 reg tile, f32x2 m-pairs.
//   out[dir][m][n] = W_dir[n][:] . A_row(m) + bias_dir[n]
// ---------------------------------------------------------------------------
template <int KDIM, bool GATHER>
__global__ __launch_bounds__(256)
void gates_gemm_kernel(const float* __restrict__ A, const int* __restrict__ xids,
                       const float* __restrict__ Wf, const float* __restrict__ Wb,
                       const float* __restrict__ bf, const float* __restrict__ bb,
                       float* __restrict__ out) {
    const int m0 = blockIdx.x * 128;
    const int n0 = blockIdx.y * 96;
    const int dir = blockIdx.z;
    const float* W = dir ? Wb : Wf;
    const float* bias = dir ? bb : bf;
    float* outp = out + (size_t)dir * Mrows * G3;

    __shared__ float As[16][128];   // [k][m]
    __shared__ float Bs[16][96];    // [k][n]
    __shared__ int rid[128];

    const int tid = threadIdx.x;
    if (GATHER && tid < 128) {
        int m = m0 + tid;
        rid[tid] = xids[(m & 255) * Tt + (m >> 8)];
    }
    if (GATHER) __syncthreads();

    const int ty = tid >> 4;       // 0..15 -> m = ty*8 .. +7
    const int tx = tid & 15;       // 0..15 -> n = tx*6 .. +5

    u64 acc[4][6];
#pragma unroll
    for (int i = 0; i < 4; i++)
#pragma unroll
        for (int j = 0; j < 6; j++) acc[i][j] = 0ull;

    // per-thread load coordinates
    const int rA0 = tid >> 2, cA = tid & 3;          // A: idx = tid, tid+256
    const int rA1 = (tid + 256) >> 2;
    const int rB = tid >> 2;                          // B: only idx<384 -> tid<384? two slots
    // B slots: idx0 = tid (always <384? no, tid up to 255 ok), idx1 = tid+256 (<384 iff tid<128)
    float4 aR0, aR1, bR0, bR1;

    const float* arow0 = GATHER ? nullptr : A + (size_t)(m0 + rA0) * KDIM;
    const float* arow1 = GATHER ? nullptr : A + (size_t)(m0 + rA1) * KDIM;

    const int KT = KDIM / 16;

    // prologue load tile 0
    {
        const float* p0 = GATHER ? A + (size_t)rid[rA0] * KDIM : arow0;
        const float* p1 = GATHER ? A + (size_t)rid[rA1] * KDIM : arow1;
        aR0 = *(const float4*)(p0 + cA * 4);
        aR1 = *(const float4*)(p1 + cA * 4);
        bR0 = *(const float4*)(W + (size_t)(n0 + rB) * KDIM + cA * 4);
        if (tid < 128)
            bR1 = *(const float4*)(W + (size_t)(n0 + rB + 64) * KDIM + cA * 4);
    }

    for (int kt = 0; kt < KT; kt++) {
        __syncthreads();   // previous compute done, smem free
        // store staged regs -> smem
        As[cA * 4 + 0][rA0] = aR0.x; As[cA * 4 + 1][rA0] = aR0.y;
        As[cA * 4 + 2][rA0] = aR0.z; As[cA * 4 + 3][rA0] = aR0.w;
        As[cA * 4 + 0][rA1] = aR1.x; As[cA * 4 + 1][rA1] = aR1.y;
        As[cA * 4 + 2][rA1] = aR1.z; As[cA * 4 + 3][rA1] = aR1.w;
        Bs[cA * 4 + 0][rB] = bR0.x; Bs[cA * 4 + 1][rB] = bR0.y;
        Bs[cA * 4 + 2][rB] = bR0.z; Bs[cA * 4 + 3][rB] = bR0.w;
        if (tid < 128) {
            Bs[cA * 4 + 0][rB + 64] = bR1.x; Bs[cA * 4 + 1][rB + 64] = bR1.y;
            Bs[cA * 4 + 2][rB + 64] = bR1.z; Bs[cA * 4 + 3][rB + 64] = bR1.w;
        }
        __syncthreads();

        // prefetch next tile into regs (overlaps compute)
        if (kt + 1 < KT) {
            int ko = (kt + 1) * 16 + cA * 4;
            const float* p0 = GATHER ? A + (size_t)rid[rA0] * KDIM : arow0;
            const float* p1 = GATHER ? A + (size_t)rid[rA1] * KDIM : arow1;
            aR0 = *(const float4*)(p0 + ko);
            aR1 = *(const float4*)(p1 + ko);
            bR0 = *(const float4*)(W + (size_t)(n0 + rB) * KDIM + ko);
            if (tid < 128)
                bR1 = *(const float4*)(W + (size_t)(n0 + rB + 64) * KDIM + ko);
        }

        // compute 16 kk
#pragma unroll 4
        for (int kk = 0; kk < 16; kk++) {
            ulonglong2 aA = *(const ulonglong2*)&As[kk][ty * 8];
            ulonglong2 aB = *(const ulonglong2*)&As[kk][ty * 8 + 4];
            u64 ap0 = aA.x, ap1 = aA.y, ap2 = aB.x, ap3 = aB.y;
            const float* bp = &Bs[kk][tx * 6];
#pragma unroll
            for (int j = 0; j < 6; j++) {
                u64 bd = pack2(bp[j], bp[j]);
                fma2(acc[0][j], ap0, bd);
                fma2(acc[1][j], ap1, bd);
                fma2(acc[2][j], ap2, bd);
                fma2(acc[3][j], ap3, bd);
            }
        }
    }

    float bj[6];
#pragma unroll
    for (int j = 0; j < 6; j++) bj[j] = bias[n0 + tx * 6 + j];

#pragma unroll
    for (int i = 0; i < 4; i++) {
        float v0[6], v1[6];
#pragma unroll
        for (int j = 0; j < 6; j++) unpack2(acc[i][j], v0[j], v1[j]);
        size_t row0 = (size_t)(m0 + ty * 8 + 2 * i) * G3 + n0 + tx * 6;
        size_t row1 = row0 + G3;
#pragma unroll
        for (int j = 0; j < 6; j++) {
            outp[row0 + j] = v0[j] + bj[j];
            outp[row1 + j] = v1[j] + bj[j];
        }
    }
}

// ---------------------------------------------------------------------------
// K2/K4: GRU scan. grid=(64,2), 160 threads. Thread g owns h-unit g, rows
// {g, g+160, g+320}. k-parity f32x2 packing: w and h pairs both come free
// from 16B vector loads. 26 k-quads of Whh in smem, 14 streamed from L2.
// ---------------------------------------------------------------------------
__global__ __launch_bounds__(160)
void scan_kernel(const float* __restrict__ gi, const float* __restrict__ wp,
                 const float* __restrict__ bhf, const float* __restrict__ bhb,
                 float* __restrict__ yout, int layer) {
    extern __shared__ char smraw[];
    ulonglong2* ws = (ulonglong2*)smraw;                       // [SKQ*480]
    float* hbuf = (float*)(smraw + (size_t)SKQ * 480 * 16);    // [2][4][160]

    const int dir = blockIdx.y;
    const int b0 = blockIdx.x * 4;
    const int g = threadIdx.x;     // 0..159

    const ulonglong2* wsrc = (const ulonglong2*)wp + (size_t)(layer * 2 + dir) * 40 * G3;
    for (int i = g; i < SKQ * G3; i += 160) ws[i] = wsrc[i];

    const float* bh = dir ? bhb : bhf;
    const float bhr = bh[g], bhz = bh[Hh + g], bhn = bh[2 * Hh + g];

    float hprev[4] = {0.f, 0.f, 0.f, 0.f};
#pragma unroll
    for (int b = 0; b < 4; b++) hbuf[b * Hh + g] = 0.f;
    __syncthreads();

    const float* gib = gi + (size_t)dir * Mrows * G3;
    int cur = 0;

    for (int s = 0; s < Tt; s++) {
        const int t = dir ? (Tt - 1 - s) : s;
        const float* gr = gib + ((size_t)t * Bb + b0) * G3;

        // prefetch input gates (DRAM) - consumed after the dot loops
        float gir[4], giz[4], gin[4];
#pragma unroll
        for (int b = 0; b < 4; b++) {
            gir[b] = gr[b * G3 + g];
            giz[b] = gr[b * G3 + Hh + g];
            gin[b] = gr[b * G3 + 2 * Hh + g];
        }

        u64 acc[3][4];
#pragma unroll
        for (int rI = 0; rI < 3; rI++)
#pragma unroll
            for (int b = 0; b < 4; b++) acc[rI][b] = 0ull;

        const float* hc = hbuf + cur * 640;

        // ---- gmem half (kq = SKQ..39), prefetch one kq ahead ----
        {
            ulonglong2 w0n = wsrc[SKQ * G3 + g];
            ulonglong2 w1n = wsrc[SKQ * G3 + Hh + g];
            ulonglong2 w2n = wsrc[SKQ * G3 + 2 * Hh + g];
#pragma unroll 2
            for (int kq = SKQ; kq < 40; kq++) {
                ulonglong2 w0 = w0n, w1 = w1n, w2 = w2n;
                if (kq < 39) {
                    int o = (kq + 1) * G3;
                    w0n = wsrc[o + g];
                    w1n = wsrc[o + Hh + g];
                    w2n = wsrc[o + 2 * Hh + g];
                }
#pragma unroll
                for (int b = 0; b < 4; b++) {
                    ulonglong2 hv = *(const ulonglong2*)&hc[b * Hh + kq * 4];
                    fma2(acc[0][b], w0.x, hv.x); fma2(acc[0][b], w0.y, hv.y);
                    fma2(acc[1][b], w1.x, hv.x); fma2(acc[1][b], w1.y, hv.y);
                    fma2(acc[2][b], w2.x, hv.x); fma2(acc[2][b], w2.y, hv.y);
                }
            }
        }
        // ---- smem half (kq = 0..SKQ-1) ----
#pragma unroll 2
        for (int kq = 0; kq < SKQ; kq++) {
            ulonglong2 w0 = ws[kq * G3 + g];
            ulonglong2 w1 = ws[kq * G3 + Hh + g];
            ulonglong2 w2 = ws[kq * G3 + 2 * Hh + g];
#pragma unroll
            for (int b = 0; b < 4; b++) {
                ulonglong2 hv = *(const ulonglong2*)&hc[b * Hh + kq * 4];
                fma2(acc[0][b], w0.x, hv.x); fma2(acc[0][b], w0.y, hv.y);
                fma2(acc[1][b], w1.x, hv.x); fma2(acc[1][b], w1.y, hv.y);
                fma2(acc[2][b], w2.x, hv.x); fma2(acc[2][b], w2.y, hv.y);
            }
        }

        // ---- gate combine + h update (all local) ----
        float* hn = hbuf + (cur ^ 1) * 640;
#pragma unroll
        for (int b = 0; b < 4; b++) {
            float lr, hr, lz, hz, ln, hnv;
            unpack2(acc[0][b], lr, hr);
            unpack2(acc[1][b], lz, hz);
            unpack2(acc[2][b], ln, hnv);
            float ghr = lr + hr + bhr;
            float ghz = lz + hz + bhz;
            float ghn = ln + hnv + bhn;
            float r = sigm_f(gir[b] + ghr);
            float z = sigm_f(giz[b] + ghz);
            float n = tanhf(gin[b] + r * ghn);
            float hnew = (1.f - z) * n + z * hprev[b];
            hprev[b] = hnew;
            hn[b * Hh + g] = hnew;
            if (layer == 0) {
                yout[((size_t)t * Bb + b0 + b) * 320 + dir * Hh + g] = hnew;
            }
        }
        __syncthreads();
        cur ^= 1;
    }

    if (layer == 1) {
#pragma unroll
        for (int b = 0; b < 4; b++)
            yout[((size_t)dir * Bb + b0 + b) * Hh + g] = hprev[b];
    }
}

// ---------------------------------------------------------------------------
// K5: head
// ---------------------------------------------------------------------------
__global__ __launch_bounds__(128)
void head_kernel(const float* __restrict__ hfin,
                 const float* __restrict__ fc1w, const float* __restrict__ fc1b,
                 const float* __restrict__ fc2w, const float* __restrict__ fc2b,
                 float* __restrict__ out) {
    const int b = blockIdx.x;
    const int j = threadIdx.x;
    __shared__ float hv[320];
    __shared__ float red[4];

    for (int k = j; k < Hh; k += 128) {
        hv[k]      = hfin[(size_t)b * Hh + k];
        hv[Hh + k] = hfin[(size_t)Bb * Hh + (size_t)b * Hh + k];
    }
    __syncthreads();

    float acc = fc1b[j];
    const float* wr = fc1w + (size_t)j * 320;
#pragma unroll 8
    for (int k = 0; k < 320; k++) acc += wr[k] * hv[k];
    float v = fmaxf(acc, 0.f) * fc2w[j];

#pragma unroll
    for (int o = 16; o > 0; o >>= 1) v += __shfl_down_sync(0xffffffffu, v, o);
    if ((j & 31) == 0) red[j >> 5] = v;
    __syncthreads();
    if (j == 0) out[b] = red[0] + red[1] + red[2] + red[3] + fc2b[0];
}

// ---------------------------------------------------------------------------
// kernel_launch
// ---------------------------------------------------------------------------
extern "C" void kernel_launch(void* const* d_in, const int* in_sizes, int n_in,
                              void* d_out, int out_size) {
    const int*   x        = (const int*)  d_in[0];
    const float* emb      = (const float*)d_in[1];
    const float* Wih_l0f  = (const float*)d_in[2];
    const float* Whh_l0f  = (const float*)d_in[3];
    const float* bih_l0f  = (const float*)d_in[4];
    const float* bhh_l0f  = (const float*)d_in[5];
    const float* Wih_l0b  = (const float*)d_in[6];
    const float* Whh_l0b  = (const float*)d_in[7];
    const float* bih_l0b  = (const float*)d_in[8];
    const float* bhh_l0b  = (const float*)d_in[9];
    const float* Wih_l1f  = (const float*)d_in[10];
    const float* Whh_l1f  = (const float*)d_in[11];
    const float* bih_l1f  = (const float*)d_in[12];
    const float* bhh_l1f  = (const float*)d_in[13];
    const float* Wih_l1b  = (const float*)d_in[14];
    const float* Whh_l1b  = (const float*)d_in[15];
    const float* bih_l1b  = (const float*)d_in[16];
    const float* bhh_l1b  = (const float*)d_in[17];
    const float* fc1_w    = (const float*)d_in[18];
    const float* fc1_b    = (const float*)d_in[19];
    const float* fc2_w    = (const float*)d_in[20];
    const float* fc2_b    = (const float*)d_in[21];
    float* out = (float*)d_out;

    float *gi0, *gi1, *y0, *whhP, *hfin;
    cudaGetSymbolAddress((void**)&gi0,  g_gi0);
    cudaGetSymbolAddress((void**)&gi1,  g_gi1);
    cudaGetSymbolAddress((void**)&y0,   g_y0);
    cudaGetSymbolAddress((void**)&whhP, g_whhP);
    cudaGetSymbolAddress((void**)&hfin, g_hfin);

    static int smem_set = 0;
    const int scan_smem = SKQ * G3 * 16 + 2 * 4 * Hh * 4;   // 199680 + 5120
    if (!smem_set) {
        cudaFuncSetAttribute(scan_kernel, cudaFuncAttributeMaxDynamicSharedMemorySize,
                             scan_smem);
        smem_set = 1;
    }

    pack_whh_kernel<<<4, 256>>>(Whh_l0f, Whh_l0b, Whh_l1f, Whh_l1b, whhP);

    {
        dim3 grid(Mrows / 128, G3 / 96, 2);
        gates_gemm_kernel<128, true><<<grid, 256>>>(emb, x, Wih_l0f, Wih_l0b,
                                                    bih_l0f, bih_l0b, gi0);
    }

    scan_kernel<<<dim3(Bb / 4, 2), 160, scan_smem>>>(gi0, whhP, bhh_l0f, bhh_l0b, y0, 0);

    {
        dim3 grid(Mrows / 128, G3 / 96, 2);
        gates_gemm_kernel<320, false><<<grid, 256>>>(y0, nullptr, Wih_l1f, Wih_l1b,
                                                     bih_l1f, bih_l1b, gi1);
    }

    scan_kernel<<<dim3(Bb / 4, 2), 160, scan_smem>>>(gi1, whhP, bhh_l1f, bhh_l1b, hfin, 1);

    head_kernel<<<Bb, 128>>>(hfin, fc1_w, fc1_b, fc2_w, fc2_b, out);
}